// round 15
// baseline (speedup 1.0000x reference)
#include <cuda_runtime.h>
#include <cuda_fp16.h>
#include <cstdint>
#include <math.h>

#define NN 16384
#define FF 26
#define HH 512
#define NHH 8
#define HDD 64

// ---------------- scratch (device globals; no allocations) ----------------
__device__ float  g_x[NN * HH];
__device__ __half g_xh[NN * HH];        // fp16 copy of g_x (GEMM A operand)
__device__ __half g_q[NN * HH];
__device__ __half g_k[NN * HH];
__device__ __half g_v[NN * HH];
__device__ __half g_s[NN * HH];
__device__ float  g_part[128 * HH];
__device__ __half g_wh[16 * HH * HH];   // [mat][n][k], fp16 transposed weights
__device__ float  g_wbA[4 * HH];        // w0 + w2 (folded gate weights)
__device__ float  g_wbB[4 * HH];        // w1 - w2

__device__ __forceinline__ uint32_t smem_u32(const void* p) {
    uint32_t a;
    asm("{ .reg .u64 t; cvta.to.shared.u64 t, %1; cvt.u32.u64 %0, t; }" : "=r"(a) : "l"(p));
    return a;
}
__device__ __forceinline__ void cp_async16(uint32_t dst, const void* src) {
    asm volatile("cp.async.cg.shared.global [%0], [%1], 16;" :: "r"(dst), "l"(src));
}
__device__ __forceinline__ void cp_commit() {
    asm volatile("cp.async.commit_group;" ::: "memory");
}
template <int N> __device__ __forceinline__ void cp_wait() {
    asm volatile("cp.async.wait_group %0;" :: "n"(N) : "memory");
}
// fp16-accumulate mma: D(f16x2 x2) = A*B + C
__device__ __forceinline__ void mma_f16acc(uint32_t* c, const uint32_t* a, const uint32_t* b) {
    asm volatile(
        "mma.sync.aligned.m16n8k16.row.col.f16.f16.f16.f16 "
        "{%0,%1}, {%2,%3,%4,%5}, {%6,%7}, {%0,%1};"
        : "+r"(c[0]), "+r"(c[1])
        : "r"(a[0]), "r"(a[1]), "r"(a[2]), "r"(a[3]), "r"(b[0]), "r"(b[1]));
}
__device__ __forceinline__ void ldsm_x4(uint32_t* r, uint32_t addr) {
    asm volatile("ldmatrix.sync.aligned.m8n8.x4.shared.b16 {%0,%1,%2,%3}, [%4];"
        : "=r"(r[0]), "=r"(r[1]), "=r"(r[2]), "=r"(r[3]) : "r"(addr));
}
// unpack 8 halves (uint4) into 8 floats
__device__ __forceinline__ void h8f(uint4 u, float* f) {
    float2 t;
    t = __half22float2(*(__half2*)&u.x); f[0] = t.x; f[1] = t.y;
    t = __half22float2(((__half2*)&u.x)[1]); f[2] = t.x; f[3] = t.y;
    t = __half22float2(*(__half2*)&u.z); f[4] = t.x; f[5] = t.y;
    t = __half22float2(((__half2*)&u.z)[1]); f[6] = t.x; f[7] = t.y;
}

// ---------------- weight transpose + fp16 conversion ----------------
__global__ __launch_bounds__(256) void transpose_w(
    const float* __restrict__ Wq, const float* __restrict__ Wk,
    const float* __restrict__ Wv, const float* __restrict__ Ws_)
{
    int mat = blockIdx.z;
    int layer = mat >> 2, sel = mat & 3;
    const float* W = (sel == 0) ? Wq : (sel == 1) ? Wk : (sel == 2) ? Wv : Ws_;
    W += (size_t)layer * HH * HH;
    __half* out = g_wh + (size_t)mat * HH * HH;

    __shared__ float t[32][33];
    int tx = threadIdx.x & 31, ty = threadIdx.x >> 5;
    int n0 = blockIdx.x * 32, k0 = blockIdx.y * 32;
#pragma unroll
    for (int i = 0; i < 32; i += 8)
        t[ty + i][tx] = W[(size_t)(k0 + ty + i) * HH + n0 + tx];
    __syncthreads();
#pragma unroll
    for (int i = 0; i < 32; i += 8)
        out[(size_t)(n0 + ty + i) * HH + k0 + tx] = __float2half(t[tx][ty + i]);
}

// ---------------- fold gate weights: wA = w0+w2, wB = w1-w2 ----------------
__global__ __launch_bounds__(512) void prep_wb(const float* __restrict__ Wb)
{
    int l = blockIdx.x, j = threadIdx.x;
    const float* w = Wb + (size_t)l * 3 * HH;
    g_wbA[l * HH + j] = w[j] + w[2 * HH + j];
    g_wbB[l * HH + j] = w[HH + j] - w[2 * HH + j];
}

// ---------------- input projection ----------------
__global__ __launch_bounds__(256) void input_gemm(
    const float* __restrict__ A, const float* __restrict__ Wp,
    const float* __restrict__ bp)
{
    int n = blockIdx.x;
    __shared__ float a[FF];
    if (threadIdx.x < FF) a[threadIdx.x] = A[n * FF + threadIdx.x];
    __syncthreads();
    int j = threadIdx.x * 2;
    float2 acc = *(const float2*)(bp + j);
#pragma unroll
    for (int kk = 0; kk < FF; kk++) {
        float2 w = *(const float2*)(Wp + kk * HH + j);
        acc.x += a[kk] * w.x;
        acc.y += a[kk] * w.y;
    }
    *(float2*)(g_x + n * HH + j) = acc;
    *(__half2*)(g_xh + n * HH + j) = __floats2half2_rn(acc.x, acc.y);
}

// ---------------- fp16 mma.sync GEMM, fp16-accum K=32 chunks ---------------
// CTA tile 128(M) x 256(N) x 64(K), 8 warps 2x4, warp tile 64x64. 256 thr.
// acc16 (fp16) accumulates 2 consecutive k16 mmas, then promotes to fp32.
#define ASH 72                                  // smem stride in halves
#define A_HALVES (128 * ASH)
#define B_HALVES (256 * ASH)
#define STAGE_HALVES (A_HALVES + B_HALVES)
#define GEMM_SMEM (4 * STAGE_HALVES * 2)

__global__ __launch_bounds__(256) void qkvs_gemm_mma(
    int layer,
    const float* __restrict__ bq, const float* __restrict__ bk,
    const float* __restrict__ bv, const float* __restrict__ bs_)
{
    extern __shared__ __half smh[];
    uint32_t smb = smem_u32(smh);

    int tid = threadIdx.x;
    int ntile = blockIdx.x;          // 0..1
    int mtile = blockIdx.y;          // 0..127
    int mat   = blockIdx.z;          // 0..3

    const float* bias = (mat == 0) ? bq : (mat == 1) ? bk : (mat == 2) ? bv : bs_;
    bias += (size_t)layer * HH + ntile * 256;
    __half* C = (mat == 0) ? g_q : (mat == 1) ? g_k : (mat == 2) ? g_v : g_s;
    const __half* Asrc = g_xh + (size_t)mtile * 128 * HH;
    const __half* Bsrc = g_wh + ((size_t)(layer * 4 + mat) * HH + ntile * 256) * HH;

    int w = tid >> 5, lane = tid & 31;
    int wm = w >> 2, wn = w & 3;                 // 2 x 4 warp grid
    int g = lane >> 2, tig = lane & 3;

    float acc[4][8][4];
#pragma unroll
    for (int i = 0; i < 4; i++)
#pragma unroll
        for (int j = 0; j < 8; j++)
#pragma unroll
            for (int c = 0; c < 4; c++) acc[i][j][c] = 0.f;

    uint32_t a_lane_off = (uint32_t)(((wm * 64 + (lane & 15)) * ASH + (lane >> 4) * 8) * 2);
    uint32_t b_lane_off = (uint32_t)(A_HALVES * 2 +
        ((wn * 64 + (lane & 7) + (lane >> 4) * 8) * ASH + ((lane >> 3) & 1) * 8) * 2);

    auto load_stage = [&](int s, int buf) {
        int k0 = s * 64;
        uint32_t base = smb + (uint32_t)(buf * STAGE_HALVES) * 2;
#pragma unroll
        for (int i = 0; i < 4; i++) {          // A: 128 rows x 8 chunks
            int q = tid + i * 256;
            int row = q >> 3, c = q & 7;
            cp_async16(base + (uint32_t)(row * ASH + c * 8) * 2,
                       Asrc + (size_t)row * HH + k0 + c * 8);
        }
#pragma unroll
        for (int i = 0; i < 8; i++) {          // B: 256 rows x 8 chunks
            int q = tid + i * 256;
            int row = q >> 3, c = q & 7;
            cp_async16(base + (uint32_t)(A_HALVES + row * ASH + c * 8) * 2,
                       Bsrc + (size_t)row * HH + k0 + c * 8);
        }
        cp_commit();
    };

    auto compute = [&](int buf) {
        uint32_t stage = smb + (uint32_t)(buf * STAGE_HALVES) * 2;
        uint32_t abase = stage + a_lane_off;
        uint32_t bbase = stage + b_lane_off;
        uint32_t acc16[4][8][2];
#pragma unroll
        for (int kk = 0; kk < 4; kk++) {       // 4 x k16; promote every 2
            uint32_t kbb = kk * 32;            // 16 halves = 32 bytes
            uint32_t af[4][4], bf[8][2];
#pragma unroll
            for (int i = 0; i < 4; i++)
                ldsm_x4(af[i], abase + (uint32_t)(i * 16 * ASH * 2) + kbb);
#pragma unroll
            for (int p = 0; p < 4; p++)
                ldsm_x4(&bf[p * 2][0], bbase + (uint32_t)(p * 16 * ASH * 2) + kbb);
            if ((kk & 1) == 0) {               // chunk start: clear fp16 accs
#pragma unroll
                for (int i = 0; i < 4; i++)
#pragma unroll
                    for (int j = 0; j < 8; j++) { acc16[i][j][0] = 0u; acc16[i][j][1] = 0u; }
            }
#pragma unroll
            for (int i = 0; i < 4; i++)
#pragma unroll
                for (int j = 0; j < 8; j++) mma_f16acc(acc16[i][j], af[i], bf[j]);
            if ((kk & 1) == 1) {               // chunk end: promote to fp32
#pragma unroll
                for (int i = 0; i < 4; i++)
#pragma unroll
                    for (int j = 0; j < 8; j++) {
                        float2 lo = __half22float2(*(__half2*)&acc16[i][j][0]);
                        float2 hi = __half22float2(*(__half2*)&acc16[i][j][1]);
                        acc[i][j][0] += lo.x; acc[i][j][1] += lo.y;
                        acc[i][j][2] += hi.x; acc[i][j][3] += hi.y;
                    }
            }
        }
    };

    load_stage(0, 0);
    load_stage(1, 1);
    load_stage(2, 2);

#pragma unroll
    for (int s = 0; s < 8; s++) {
        if (s < 6)      cp_wait<2>();
        else if (s == 6) cp_wait<1>();
        else             cp_wait<0>();
        __syncthreads();                       // also orders buf reuse (4-deep ring)
        if (s < 5) load_stage(s + 3, (s + 3) & 3);
        compute(s & 3);
    }

    // epilogue: add bias, store fp16
#pragma unroll
    for (int i = 0; i < 4; i++) {
        int row0 = mtile * 128 + wm * 64 + i * 16 + g;
#pragma unroll
        for (int j = 0; j < 8; j++) {
            int col = wn * 64 + j * 8 + 2 * tig;
            float bx = __ldg(&bias[col]), by = __ldg(&bias[col + 1]);
            __half2 o0 = __floats2half2_rn(acc[i][j][0] + bx, acc[i][j][1] + by);
            __half2 o1 = __floats2half2_rn(acc[i][j][2] + bx, acc[i][j][3] + by);
            *(__half2*)(C + (size_t)row0 * HH + ntile * 256 + col) = o0;
            *(__half2*)(C + (size_t)(row0 + 8) * HH + ntile * 256 + col) = o1;
        }
    }
}

// ---------------- fused attention + gate + residual + LayerNorm ----------------
// WARP-PER-NODE; all bulk loads hoisted (MLP ~16).
__global__ __launch_bounds__(128) void attn_gate_ln(
    const float* __restrict__ wbA, const float* __restrict__ wbB,
    const float* __restrict__ lg, const float* __restrict__ lb,
    float* __restrict__ dout, int is_last)
{
    int node = blockIdx.x * 4 + (threadIdx.x >> 5);
    int lane = threadIdx.x & 31;
    int e0 = lane * 16;                       // channel base

    int i = node >> 7, j = node & 127;
    int nb[4];
    float msk[4];
    nb[0] = (i > 0)   ? node - 128 : node;  msk[0] = (i > 0)   ? 0.f : -1e30f;
    nb[1] = (i < 127) ? node + 128 : node;  msk[1] = (i < 127) ? 0.f : -1e30f;
    nb[2] = (j > 0)   ? node - 1   : node;  msk[2] = (j > 0)   ? 0.f : -1e30f;
    nb[3] = (j < 127) ? node + 1   : node;  msk[3] = (j < 127) ? 0.f : -1e30f;

    // ======== hoisted loads ========
    const uint4* qp = (const uint4*)(g_q + (size_t)node * HH + e0);
    uint4 qa = qp[0], qb = qp[1];
    uint4 ka[4], kb2[4], va[4], vb[4];
#pragma unroll
    for (int t = 0; t < 4; t++) {
        const uint4* kp = (const uint4*)(g_k + (size_t)nb[t] * HH + e0);
        ka[t] = kp[0]; kb2[t] = kp[1];
    }
#pragma unroll
    for (int t = 0; t < 4; t++) {
        const uint4* vp = (const uint4*)(g_v + (size_t)nb[t] * HH + e0);
        va[t] = vp[0]; vb[t] = vp[1];
    }
    const uint4* sp = (const uint4*)(g_s + (size_t)node * HH + e0);
    uint4 sa = sp[0], sb = sp[1];
    float4 xv0 = ((const float4*)(g_x + (size_t)node * HH + e0))[0];
    float4 xv1 = ((const float4*)(g_x + (size_t)node * HH + e0))[1];
    float4 xv2 = ((const float4*)(g_x + (size_t)node * HH + e0))[2];
    float4 xv3 = ((const float4*)(g_x + (size_t)node * HH + e0))[3];
    float4 wA0 = ((const float4*)(wbA + e0))[0];
    float4 wA1 = ((const float4*)(wbA + e0))[1];
    float4 wA2 = ((const float4*)(wbA + e0))[2];
    float4 wA3 = ((const float4*)(wbA + e0))[3];
    float4 wB0 = ((const float4*)(wbB + e0))[0];
    float4 wB1 = ((const float4*)(wbB + e0))[1];
    float4 wB2 = ((const float4*)(wbB + e0))[2];
    float4 wB3 = ((const float4*)(wbB + e0))[3];

    // ======== dots + softmax ========
    float qf[16];
    h8f(qa, qf); h8f(qb, qf + 8);
    float d[4];
#pragma unroll
    for (int t = 0; t < 4; t++) {
        float kf[16];
        h8f(ka[t], kf); h8f(kb2[t], kf + 8);
        float s = 0.f;
#pragma unroll
        for (int e = 0; e < 16; e++) s += qf[e] * kf[e];
        d[t] = s;
    }
#pragma unroll
    for (int t = 0; t < 4; t++) {
        d[t] += __shfl_xor_sync(0xffffffffu, d[t], 1);
        d[t] += __shfl_xor_sync(0xffffffffu, d[t], 2);
        d[t] = d[t] * 0.125f + msk[t];
    }
    float m = fmaxf(fmaxf(d[0], d[1]), fmaxf(d[2], d[3]));
    float w0 = expf(d[0] - m), w1 = expf(d[1] - m);
    float w2 = expf(d[2] - m), w3 = expf(d[3] - m);
    float inv = 1.f / (w0 + w1 + w2 + w3 + 1e-16f);
    float wt[4] = {w0 * inv, w1 * inv, w2 * inv, w3 * inv};

    // ======== weighted V ========
    float o[16];
#pragma unroll
    for (int e = 0; e < 16; e++) o[e] = 0.f;
#pragma unroll
    for (int t = 0; t < 4; t++) {
        float vf[16];
        h8f(va[t], vf); h8f(vb[t], vf + 8);
#pragma unroll
        for (int e = 0; e < 16; e++) o[e] += wt[t] * vf[e];
    }

    // ======== gate (folded weights) ========
    float rv[16];
    h8f(sa, rv); h8f(sb, rv + 8);
    float wA[16] = {wA0.x, wA0.y, wA0.z, wA0.w, wA1.x, wA1.y, wA1.z, wA1.w,
                    wA2.x, wA2.y, wA2.z, wA2.w, wA3.x, wA3.y, wA3.z, wA3.w};
    float wB[16] = {wB0.x, wB0.y, wB0.z, wB0.w, wB1.x, wB1.y, wB1.z, wB1.w,
                    wB2.x, wB2.y, wB2.z, wB2.w, wB3.x, wB3.y, wB3.z, wB3.w};
    float part = 0.f;
#pragma unroll
    for (int e = 0; e < 16; e++) part += o[e] * wA[e] + rv[e] * wB[e];
#pragma unroll
    for (int s = 16; s; s >>= 1) part += __shfl_xor_sync(0xffffffffu, part, s);
    float gate = 1.f / (1.f + expf(-part));

    // ======== residual + LN ========
    float xf[16] = {xv0.x, xv0.y, xv0.z, xv0.w, xv1.x, xv1.y, xv1.z, xv1.w,
                    xv2.x, xv2.y, xv2.z, xv2.w, xv3.x, xv3.y, xv3.z, xv3.w};
    float tx[16];
    float s1 = 0.f, s2 = 0.f;
#pragma unroll
    for (int e = 0; e < 16; e++) {
        float t = xf[e] + gate * rv[e] + (1.f - gate) * o[e];
        tx[e] = t;
        s1 += t;
        s2 += t * t;
    }
#pragma unroll
    for (int s = 16; s; s >>= 1) {
        s1 += __shfl_xor_sync(0xffffffffu, s1, s);
        s2 += __shfl_xor_sync(0xffffffffu, s2, s);
    }
    float mu   = s1 * (1.f / HH);
    float var  = s2 * (1.f / HH) - mu * mu;
    float rstd = rsqrtf(var + 1e-5f);

#pragma unroll
    for (int c = 0; c < 4; c++) {
        float4 gg = ((const float4*)(lg + e0))[c];
        float4 bb = ((const float4*)(lb + e0))[c];
        float4 ov;
        ov.x = (tx[c*4+0] - mu) * rstd * gg.x + bb.x;
        ov.y = (tx[c*4+1] - mu) * rstd * gg.y + bb.y;
        ov.z = (tx[c*4+2] - mu) * rstd * gg.z + bb.z;
        ov.w = (tx[c*4+3] - mu) * rstd * gg.w + bb.w;
        if (is_last) {
            ((float4*)(dout + (size_t)node * HH + e0))[c] = ov;
        } else {
            ((float4*)(g_x + (size_t)node * HH + e0))[c] = ov;
            __half2 h0 = __floats2half2_rn(ov.x, ov.y);
            __half2 h1 = __floats2half2_rn(ov.z, ov.w);
            ((__half2*)(g_xh + (size_t)node * HH + e0))[c * 2]     = h0;
            ((__half2*)(g_xh + (size_t)node * HH + e0))[c * 2 + 1] = h1;
        }
    }
}

// ---------------- global mean ----------------
__global__ __launch_bounds__(256) void mean_stage1(const float* __restrict__ x)
{
    int b = blockIdx.x;
    int j = threadIdx.x * 2;
    float2 acc = {0.f, 0.f};
    const float* xp = x + (size_t)b * 128 * HH;
    for (int r = 0; r < 128; r++) {
        float2 v2 = *(const float2*)(xp + (size_t)r * HH + j);
        acc.x += v2.x;
        acc.y += v2.y;
    }
    *(float2*)(g_part + (size_t)b * HH + j) = acc;
}

__global__ __launch_bounds__(256) void mean_stage2(float* __restrict__ emb)
{
    int j = blockIdx.x * 256 + threadIdx.x;
    float acc = 0.f;
    for (int b = 0; b < 128; b++) acc += g_part[(size_t)b * HH + j];
    emb[j] = acc * (1.f / NN);
}

// ---------------- launch ----------------
extern "C" void kernel_launch(void* const* d_in, const int* in_sizes, int n_in,
                              void* d_out, int out_size)
{
    const float* graph = (const float*)d_in[0];
    const float* Wp = (const float*)d_in[3];
    const float* bp = (const float*)d_in[4];
    const float* Wq = (const float*)d_in[5];
    const float* bq = (const float*)d_in[6];
    const float* Wk = (const float*)d_in[7];
    const float* bk = (const float*)d_in[8];
    const float* Wv = (const float*)d_in[9];
    const float* bv = (const float*)d_in[10];
    const float* Ws = (const float*)d_in[11];
    const float* bs = (const float*)d_in[12];
    const float* Wb = (const float*)d_in[13];
    const float* lg = (const float*)d_in[14];
    const float* lb = (const float*)d_in[15];
    float* out = (float*)d_out;

    static int smem_set = 0;
    if (!smem_set) {
        cudaFuncSetAttribute(qkvs_gemm_mma, cudaFuncAttributeMaxDynamicSharedMemorySize,
                             GEMM_SMEM);
        smem_set = 1;
    }

    transpose_w<<<dim3(16, 16, 16), 256>>>(Wq, Wk, Wv, Ws);
    prep_wb<<<4, 512>>>(Wb);
    input_gemm<<<NN, 256>>>(graph, Wp, bp);

    float* wbA_dev = nullptr;
    float* wbB_dev = nullptr;
    cudaGetSymbolAddress((void**)&wbA_dev, g_wbA);
    cudaGetSymbolAddress((void**)&wbB_dev, g_wbB);

    for (int l = 0; l < 4; l++) {
        size_t bOff = (size_t)l * HH;
        qkvs_gemm_mma<<<dim3(2, 128, 4), 256, GEMM_SMEM>>>(l, bq, bk, bv, bs);
        attn_gate_ln<<<NN / 4, 128>>>(wbA_dev + bOff, wbB_dev + bOff,
                                      lg + bOff, lb + bOff,
                                      out, (l == 3) ? 1 : 0);
    }

    mean_stage1<<<128, 256>>>(out);
    mean_stage2<<<2, 256>>>(out + (size_t)NN * HH);
}

// round 16
// speedup vs baseline: 1.2423x; 1.2423x over previous
#include <cuda_runtime.h>
#include <cuda_fp16.h>
#include <cstdint>
#include <math.h>

#define NN 16384
#define FF 26
#define HH 512
#define NHH 8
#define HDD 64

// ---------------- scratch (device globals; no allocations) ----------------
__device__ float  g_x[NN * HH];
__device__ __half g_xh[NN * HH];        // fp16 copy of g_x (GEMM A operand)
__device__ __half g_q[NN * HH];
__device__ __half g_k[NN * HH];
__device__ __half g_v[NN * HH];
__device__ __half g_s[NN * HH];
__device__ float  g_part[512 * HH];
__device__ __half g_wh[16 * HH * HH];   // [mat][n][k], fp16 transposed weights
__device__ float  g_wbA[4 * HH];        // w0 + w2 (folded gate weights)
__device__ float  g_wbB[4 * HH];        // w1 - w2

__device__ __forceinline__ uint32_t smem_u32(const void* p) {
    uint32_t a;
    asm("{ .reg .u64 t; cvta.to.shared.u64 t, %1; cvt.u32.u64 %0, t; }" : "=r"(a) : "l"(p));
    return a;
}
__device__ __forceinline__ void cp_async16(uint32_t dst, const void* src) {
    asm volatile("cp.async.cg.shared.global [%0], [%1], 16;" :: "r"(dst), "l"(src));
}
__device__ __forceinline__ void cp_commit() {
    asm volatile("cp.async.commit_group;" ::: "memory");
}
template <int N> __device__ __forceinline__ void cp_wait() {
    asm volatile("cp.async.wait_group %0;" :: "n"(N) : "memory");
}
__device__ __forceinline__ void mma_f16(float* c, const uint32_t* a, const uint32_t* b) {
    asm volatile(
        "mma.sync.aligned.m16n8k16.row.col.f32.f16.f16.f32 "
        "{%0,%1,%2,%3}, {%4,%5,%6,%7}, {%8,%9}, {%0,%1,%2,%3};"
        : "+f"(c[0]), "+f"(c[1]), "+f"(c[2]), "+f"(c[3])
        : "r"(a[0]), "r"(a[1]), "r"(a[2]), "r"(a[3]), "r"(b[0]), "r"(b[1]));
}
__device__ __forceinline__ void ldsm_x4(uint32_t* r, uint32_t addr) {
    asm volatile("ldmatrix.sync.aligned.m8n8.x4.shared.b16 {%0,%1,%2,%3}, [%4];"
        : "=r"(r[0]), "=r"(r[1]), "=r"(r[2]), "=r"(r[3]) : "r"(addr));
}
// unpack 8 halves (uint4) into 8 floats
__device__ __forceinline__ void h8f(uint4 u, float* f) {
    float2 t;
    t = __half22float2(*(__half2*)&u.x); f[0] = t.x; f[1] = t.y;
    t = __half22float2(((__half2*)&u.x)[1]); f[2] = t.x; f[3] = t.y;
    t = __half22float2(*(__half2*)&u.z); f[4] = t.x; f[5] = t.y;
    t = __half22float2(((__half2*)&u.z)[1]); f[6] = t.x; f[7] = t.y;
}

// ---------------- weight transpose + fp16 conversion ----------------
__global__ __launch_bounds__(256) void transpose_w(
    const float* __restrict__ Wq, const float* __restrict__ Wk,
    const float* __restrict__ Wv, const float* __restrict__ Ws_)
{
    int mat = blockIdx.z;
    int layer = mat >> 2, sel = mat & 3;
    const float* W = (sel == 0) ? Wq : (sel == 1) ? Wk : (sel == 2) ? Wv : Ws_;
    W += (size_t)layer * HH * HH;
    __half* out = g_wh + (size_t)mat * HH * HH;

    __shared__ float t[32][33];
    int tx = threadIdx.x & 31, ty = threadIdx.x >> 5;
    int n0 = blockIdx.x * 32, k0 = blockIdx.y * 32;
#pragma unroll
    for (int i = 0; i < 32; i += 8)
        t[ty + i][tx] = W[(size_t)(k0 + ty + i) * HH + n0 + tx];
    __syncthreads();
#pragma unroll
    for (int i = 0; i < 32; i += 8)
        out[(size_t)(n0 + ty + i) * HH + k0 + tx] = __float2half(t[tx][ty + i]);
}

// ---------------- fold gate weights: wA = w0+w2, wB = w1-w2 ----------------
__global__ __launch_bounds__(512) void prep_wb(const float* __restrict__ Wb)
{
    int l = blockIdx.x, j = threadIdx.x;
    const float* w = Wb + (size_t)l * 3 * HH;
    g_wbA[l * HH + j] = w[j] + w[2 * HH + j];
    g_wbB[l * HH + j] = w[HH + j] - w[2 * HH + j];
}

// ---------------- input projection ----------------
__global__ __launch_bounds__(256) void input_gemm(
    const float* __restrict__ A, const float* __restrict__ Wp,
    const float* __restrict__ bp)
{
    int n = blockIdx.x;
    __shared__ float a[FF];
    if (threadIdx.x < FF) a[threadIdx.x] = A[n * FF + threadIdx.x];
    __syncthreads();
    int j = threadIdx.x * 2;
    float2 acc = *(const float2*)(bp + j);
#pragma unroll
    for (int kk = 0; kk < FF; kk++) {
        float2 w = *(const float2*)(Wp + kk * HH + j);
        acc.x += a[kk] * w.x;
        acc.y += a[kk] * w.y;
    }
    *(float2*)(g_x + n * HH + j) = acc;
    *(__half2*)(g_xh + n * HH + j) = __floats2half2_rn(acc.x, acc.y);
}

// ---------------- fp16 mma.sync GEMM: 512 threads, 16 warps (4x4), warp 32x64
// CTA tile 128(M) x 256(N) x 64(K), 4-stage cp.async. regs=128, no spills.
#define ASH 72                                  // smem stride in halves
#define A_HALVES (128 * ASH)
#define B_HALVES (256 * ASH)
#define STAGE_HALVES (A_HALVES + B_HALVES)
#define GEMM_SMEM (4 * STAGE_HALVES * 2)

__global__ __launch_bounds__(512) void qkvs_gemm_mma(
    int layer,
    const float* __restrict__ bq, const float* __restrict__ bk,
    const float* __restrict__ bv, const float* __restrict__ bs_)
{
    extern __shared__ __half smh[];
    uint32_t smb = smem_u32(smh);

    int tid = threadIdx.x;
    int ntile = blockIdx.x;          // 0..1
    int mtile = blockIdx.y;          // 0..127
    int mat   = blockIdx.z;          // 0..3

    const float* bias = (mat == 0) ? bq : (mat == 1) ? bk : (mat == 2) ? bv : bs_;
    bias += (size_t)layer * HH + ntile * 256;
    __half* C = (mat == 0) ? g_q : (mat == 1) ? g_k : (mat == 2) ? g_v : g_s;
    const __half* Asrc = g_xh + (size_t)mtile * 128 * HH;
    const __half* Bsrc = g_wh + ((size_t)(layer * 4 + mat) * HH + ntile * 256) * HH;

    int w = tid >> 5, lane = tid & 31;
    int wm = w >> 2, wn = w & 3;                 // 4 x 4 warp grid
    int g = lane >> 2, tig = lane & 3;

    float acc[2][8][4];                          // warp tile 32 x 64
#pragma unroll
    for (int i = 0; i < 2; i++)
#pragma unroll
        for (int j = 0; j < 8; j++)
#pragma unroll
            for (int c = 0; c < 4; c++) acc[i][j][c] = 0.f;

    uint32_t a_lane_off = (uint32_t)(((wm * 32 + (lane & 15)) * ASH + (lane >> 4) * 8) * 2);
    uint32_t b_lane_off = (uint32_t)(A_HALVES * 2 +
        ((wn * 64 + (lane & 7) + (lane >> 4) * 8) * ASH + ((lane >> 3) & 1) * 8) * 2);

    auto load_stage = [&](int s, int buf) {
        int k0 = s * 64;
        uint32_t base = smb + (uint32_t)(buf * STAGE_HALVES) * 2;
#pragma unroll
        for (int i = 0; i < 2; i++) {            // A: 1024 chunks / 512 threads
            int q = tid + i * 512;
            int row = q >> 3, c = q & 7;
            cp_async16(base + (uint32_t)(row * ASH + c * 8) * 2,
                       Asrc + (size_t)row * HH + k0 + c * 8);
        }
#pragma unroll
        for (int i = 0; i < 4; i++) {            // B: 2048 chunks / 512 threads
            int q = tid + i * 512;
            int row = q >> 3, c = q & 7;
            cp_async16(base + (uint32_t)(A_HALVES + row * ASH + c * 8) * 2,
                       Bsrc + (size_t)row * HH + k0 + c * 8);
        }
        cp_commit();
    };

    auto compute = [&](int buf) {
        uint32_t stage = smb + (uint32_t)(buf * STAGE_HALVES) * 2;
        uint32_t abase = stage + a_lane_off;
        uint32_t bbase = stage + b_lane_off;
#pragma unroll
        for (int kk = 0; kk < 4; kk++) {         // 4 x k16
            uint32_t kbb = kk * 32;
            uint32_t af[2][4], bf[8][2];
#pragma unroll
            for (int i = 0; i < 2; i++)
                ldsm_x4(af[i], abase + (uint32_t)(i * 16 * ASH * 2) + kbb);
#pragma unroll
            for (int p = 0; p < 4; p++)
                ldsm_x4(&bf[p * 2][0], bbase + (uint32_t)(p * 16 * ASH * 2) + kbb);
#pragma unroll
            for (int i = 0; i < 2; i++)
#pragma unroll
                for (int j = 0; j < 8; j++) mma_f16(acc[i][j], af[i], bf[j]);
        }
    };

    load_stage(0, 0);
    load_stage(1, 1);
    load_stage(2, 2);

#pragma unroll
    for (int s = 0; s < 8; s++) {
        if (s < 6)      cp_wait<2>();
        else if (s == 6) cp_wait<1>();
        else             cp_wait<0>();
        __syncthreads();                         // also orders buf reuse (4-deep ring)
        if (s < 5) load_stage(s + 3, (s + 3) & 3);
        compute(s & 3);
    }

    // epilogue: add bias, store fp16
#pragma unroll
    for (int i = 0; i < 2; i++) {
        int row0 = mtile * 128 + wm * 32 + i * 16 + g;
#pragma unroll
        for (int j = 0; j < 8; j++) {
            int col = wn * 64 + j * 8 + 2 * tig;
            float bx = __ldg(&bias[col]), by = __ldg(&bias[col + 1]);
            __half2 o0 = __floats2half2_rn(acc[i][j][0] + bx, acc[i][j][1] + by);
            __half2 o1 = __floats2half2_rn(acc[i][j][2] + bx, acc[i][j][3] + by);
            *(__half2*)(C + (size_t)row0 * HH + ntile * 256 + col) = o0;
            *(__half2*)(C + (size_t)(row0 + 8) * HH + ntile * 256 + col) = o1;
        }
    }
}

// ---------------- fused attention + gate + residual + LayerNorm ----------------
// WARP-PER-NODE. Only per-node DRAM data (q, k, v, s, x) is hoisted; the
// layer-uniform vectors (wbA, wbB, lg, lb) are L1-resident after first touch
// and loaded at use — lower peak registers, more resident warps.
__global__ __launch_bounds__(128) void attn_gate_ln(
    const float* __restrict__ wbA, const float* __restrict__ wbB,
    const float* __restrict__ lg, const float* __restrict__ lb,
    float* __restrict__ dout, int is_last)
{
    int node = blockIdx.x * 4 + (threadIdx.x >> 5);
    int lane = threadIdx.x & 31;
    int e0 = lane * 16;                       // channel base

    int i = node >> 7, j = node & 127;
    int nb[4];
    float msk[4];
    nb[0] = (i > 0)   ? node - 128 : node;  msk[0] = (i > 0)   ? 0.f : -1e30f;
    nb[1] = (i < 127) ? node + 128 : node;  msk[1] = (i < 127) ? 0.f : -1e30f;
    nb[2] = (j > 0)   ? node - 1   : node;  msk[2] = (j > 0)   ? 0.f : -1e30f;
    nb[3] = (j < 127) ? node + 1   : node;  msk[3] = (j < 127) ? 0.f : -1e30f;

    // ======== hoisted per-node DRAM loads ========
    const uint4* qp = (const uint4*)(g_q + (size_t)node * HH + e0);
    uint4 qa = qp[0], qb = qp[1];
    uint4 ka[4], kb2[4], va[4], vb[4];
#pragma unroll
    for (int t = 0; t < 4; t++) {
        const uint4* kp = (const uint4*)(g_k + (size_t)nb[t] * HH + e0);
        ka[t] = kp[0]; kb2[t] = kp[1];
    }
#pragma unroll
    for (int t = 0; t < 4; t++) {
        const uint4* vp = (const uint4*)(g_v + (size_t)nb[t] * HH + e0);
        va[t] = vp[0]; vb[t] = vp[1];
    }
    const uint4* sp = (const uint4*)(g_s + (size_t)node * HH + e0);
    uint4 sa = sp[0], sb = sp[1];
    float4 xv0 = ((const float4*)(g_x + (size_t)node * HH + e0))[0];
    float4 xv1 = ((const float4*)(g_x + (size_t)node * HH + e0))[1];
    float4 xv2 = ((const float4*)(g_x + (size_t)node * HH + e0))[2];
    float4 xv3 = ((const float4*)(g_x + (size_t)node * HH + e0))[3];

    // ======== dots + softmax ========
    float qf[16];
    h8f(qa, qf); h8f(qb, qf + 8);
    float d[4];
#pragma unroll
    for (int t = 0; t < 4; t++) {
        float kf[16];
        h8f(ka[t], kf); h8f(kb2[t], kf + 8);
        float s = 0.f;
#pragma unroll
        for (int e = 0; e < 16; e++) s += qf[e] * kf[e];
        d[t] = s;
    }
#pragma unroll
    for (int t = 0; t < 4; t++) {
        d[t] += __shfl_xor_sync(0xffffffffu, d[t], 1);
        d[t] += __shfl_xor_sync(0xffffffffu, d[t], 2);
        d[t] = d[t] * 0.125f + msk[t];
    }
    float m = fmaxf(fmaxf(d[0], d[1]), fmaxf(d[2], d[3]));
    float w0 = expf(d[0] - m), w1 = expf(d[1] - m);
    float w2 = expf(d[2] - m), w3 = expf(d[3] - m);
    float inv = 1.f / (w0 + w1 + w2 + w3 + 1e-16f);
    float wt[4] = {w0 * inv, w1 * inv, w2 * inv, w3 * inv};

    // ======== weighted V ========
    float o[16];
#pragma unroll
    for (int e = 0; e < 16; e++) o[e] = 0.f;
#pragma unroll
    for (int t = 0; t < 4; t++) {
        float vf[16];
        h8f(va[t], vf); h8f(vb[t], vf + 8);
#pragma unroll
        for (int e = 0; e < 16; e++) o[e] += wt[t] * vf[e];
    }

    // ======== gate (folded weights, L1-resident loads at use) ========
    float rv[16];
    h8f(sa, rv); h8f(sb, rv + 8);
    float part = 0.f;
#pragma unroll
    for (int c = 0; c < 4; c++) {
        float4 a4 = ((const float4*)(wbA + e0))[c];
        float4 b4 = ((const float4*)(wbB + e0))[c];
        const float* pa = (const float*)&a4;
        const float* pb = (const float*)&b4;
#pragma unroll
        for (int u = 0; u < 4; u++) {
            int e = c * 4 + u;
            part += o[e] * pa[u] + rv[e] * pb[u];
        }
    }
#pragma unroll
    for (int s = 16; s; s >>= 1) part += __shfl_xor_sync(0xffffffffu, part, s);
    float gate = 1.f / (1.f + expf(-part));

    // ======== residual + LN ========
    float xf[16] = {xv0.x, xv0.y, xv0.z, xv0.w, xv1.x, xv1.y, xv1.z, xv1.w,
                    xv2.x, xv2.y, xv2.z, xv2.w, xv3.x, xv3.y, xv3.z, xv3.w};
    float tx[16];
    float s1 = 0.f, s2 = 0.f;
#pragma unroll
    for (int e = 0; e < 16; e++) {
        float t = xf[e] + gate * rv[e] + (1.f - gate) * o[e];
        tx[e] = t;
        s1 += t;
        s2 += t * t;
    }
#pragma unroll
    for (int s = 16; s; s >>= 1) {
        s1 += __shfl_xor_sync(0xffffffffu, s1, s);
        s2 += __shfl_xor_sync(0xffffffffu, s2, s);
    }
    float mu   = s1 * (1.f / HH);
    float var  = s2 * (1.f / HH) - mu * mu;
    float rstd = rsqrtf(var + 1e-5f);

#pragma unroll
    for (int c = 0; c < 4; c++) {
        float4 gg = ((const float4*)(lg + e0))[c];
        float4 bb = ((const float4*)(lb + e0))[c];
        float4 ov;
        ov.x = (tx[c*4+0] - mu) * rstd * gg.x + bb.x;
        ov.y = (tx[c*4+1] - mu) * rstd * gg.y + bb.y;
        ov.z = (tx[c*4+2] - mu) * rstd * gg.z + bb.z;
        ov.w = (tx[c*4+3] - mu) * rstd * gg.w + bb.w;
        if (is_last) {
            ((float4*)(dout + (size_t)node * HH + e0))[c] = ov;
        } else {
            ((float4*)(g_x + (size_t)node * HH + e0))[c] = ov;
            __half2 h0 = __floats2half2_rn(ov.x, ov.y);
            __half2 h1 = __floats2half2_rn(ov.z, ov.w);
            ((__half2*)(g_xh + (size_t)node * HH + e0))[c * 2]     = h0;
            ((__half2*)(g_xh + (size_t)node * HH + e0))[c * 2 + 1] = h1;
        }
    }
}

// ---------------- global mean ----------------
__global__ __launch_bounds__(256) void mean_stage1(const float* __restrict__ x)
{
    int b = blockIdx.x;                      // 0..511, rows b*32..b*32+31
    int j = threadIdx.x * 2;
    float2 acc = {0.f, 0.f};
    const float* xp = x + (size_t)b * 32 * HH;
    for (int r = 0; r < 32; r++) {
        float2 v2 = *(const float2*)(xp + (size_t)r * HH + j);
        acc.x += v2.x;
        acc.y += v2.y;
    }
    *(float2*)(g_part + (size_t)b * HH + j) = acc;
}

__global__ __launch_bounds__(256) void mean_stage2(float* __restrict__ emb)
{
    int j = blockIdx.x * 256 + threadIdx.x;
    float acc = 0.f;
    for (int b = 0; b < 512; b++) acc += g_part[(size_t)b * HH + j];
    emb[j] = acc * (1.f / NN);
}

// ---------------- launch ----------------
extern "C" void kernel_launch(void* const* d_in, const int* in_sizes, int n_in,
                              void* d_out, int out_size)
{
    const float* graph = (const float*)d_in[0];
    const float* Wp = (const float*)d_in[3];
    const float* bp = (const float*)d_in[4];
    const float* Wq = (const float*)d_in[5];
    const float* bq = (const float*)d_in[6];
    const float* Wk = (const float*)d_in[7];
    const float* bk = (const float*)d_in[8];
    const float* Wv = (const float*)d_in[9];
    const float* bv = (const float*)d_in[10];
    const float* Ws = (const float*)d_in[11];
    const float* bs = (const float*)d_in[12];
    const float* Wb = (const float*)d_in[13];
    const float* lg = (const float*)d_in[14];
    const float* lb = (const float*)d_in[15];
    float* out = (float*)d_out;

    static int smem_set = 0;
    if (!smem_set) {
        cudaFuncSetAttribute(qkvs_gemm_mma, cudaFuncAttributeMaxDynamicSharedMemorySize,
                             GEMM_SMEM);
        smem_set = 1;
    }

    transpose_w<<<dim3(16, 16, 16), 256>>>(Wq, Wk, Wv, Ws);
    prep_wb<<<4, 512>>>(Wb);
    input_gemm<<<NN, 256>>>(graph, Wp, bp);

    float* wbA_dev = nullptr;
    float* wbB_dev = nullptr;
    cudaGetSymbolAddress((void**)&wbA_dev, g_wbA);
    cudaGetSymbolAddress((void**)&wbB_dev, g_wbB);

    for (int l = 0; l < 4; l++) {
        size_t bOff = (size_t)l * HH;
        qkvs_gemm_mma<<<dim3(2, 128, 4), 512, GEMM_SMEM>>>(l, bq, bk, bv, bs);
        attn_gate_ln<<<NN / 4, 128>>>(wbA_dev + bOff, wbB_dev + bOff,
                                      lg + bOff, lb + bOff,
                                      out, (l == 3) ? 1 : 0);
    }

    mean_stage1<<<512, 256>>>(out);
    mean_stage2<<<2, 256>>>(out + (size_t)NN * HH);
}

// round 17
// speedup vs baseline: 1.3463x; 1.0837x over previous
#include <cuda_runtime.h>
#include <cuda_fp16.h>
#include <cstdint>
#include <math.h>

#define NN 16384
#define FF 26
#define HH 512
#define NHH 8
#define HDD 64

// ---------------- scratch (device globals; no allocations) ----------------
__device__ __half g_xh[NN * HH];        // fp16 residual / GEMM A operand
__device__ __half g_q[NN * HH];
__device__ __half g_k[NN * HH];
__device__ __half g_v[NN * HH];
__device__ __half g_s[NN * HH];
__device__ float  g_part[512 * HH];
__device__ __half g_wh[16 * HH * HH];   // [mat][n][k], fp16 transposed weights
__device__ float  g_wbA[4 * HH];        // w0 + w2 (folded gate weights)
__device__ float  g_wbB[4 * HH];        // w1 - w2

__device__ __forceinline__ uint32_t smem_u32(const void* p) {
    uint32_t a;
    asm("{ .reg .u64 t; cvta.to.shared.u64 t, %1; cvt.u32.u64 %0, t; }" : "=r"(a) : "l"(p));
    return a;
}
__device__ __forceinline__ void cp_async16(uint32_t dst, const void* src) {
    asm volatile("cp.async.cg.shared.global [%0], [%1], 16;" :: "r"(dst), "l"(src));
}
__device__ __forceinline__ void cp_commit() {
    asm volatile("cp.async.commit_group;" ::: "memory");
}
template <int N> __device__ __forceinline__ void cp_wait() {
    asm volatile("cp.async.wait_group %0;" :: "n"(N) : "memory");
}
__device__ __forceinline__ void mma_f16(float* c, const uint32_t* a, const uint32_t* b) {
    asm volatile(
        "mma.sync.aligned.m16n8k16.row.col.f32.f16.f16.f32 "
        "{%0,%1,%2,%3}, {%4,%5,%6,%7}, {%8,%9}, {%0,%1,%2,%3};"
        : "+f"(c[0]), "+f"(c[1]), "+f"(c[2]), "+f"(c[3])
        : "r"(a[0]), "r"(a[1]), "r"(a[2]), "r"(a[3]), "r"(b[0]), "r"(b[1]));
}
__device__ __forceinline__ void ldsm_x4(uint32_t* r, uint32_t addr) {
    asm volatile("ldmatrix.sync.aligned.m8n8.x4.shared.b16 {%0,%1,%2,%3}, [%4];"
        : "=r"(r[0]), "=r"(r[1]), "=r"(r[2]), "=r"(r[3]) : "r"(addr));
}
// unpack 8 halves (uint4) into 8 floats
__device__ __forceinline__ void h8f(uint4 u, float* f) {
    float2 t;
    t = __half22float2(*(__half2*)&u.x); f[0] = t.x; f[1] = t.y;
    t = __half22float2(((__half2*)&u.x)[1]); f[2] = t.x; f[3] = t.y;
    t = __half22float2(*(__half2*)&u.z); f[4] = t.x; f[5] = t.y;
    t = __half22float2(((__half2*)&u.z)[1]); f[6] = t.x; f[7] = t.y;
}

// ---------------- weight transpose + fp16 conversion ----------------
__global__ __launch_bounds__(256) void transpose_w(
    const float* __restrict__ Wq, const float* __restrict__ Wk,
    const float* __restrict__ Wv, const float* __restrict__ Ws_)
{
    int mat = blockIdx.z;
    int layer = mat >> 2, sel = mat & 3;
    const float* W = (sel == 0) ? Wq : (sel == 1) ? Wk : (sel == 2) ? Wv : Ws_;
    W += (size_t)layer * HH * HH;
    __half* out = g_wh + (size_t)mat * HH * HH;

    __shared__ float t[32][33];
    int tx = threadIdx.x & 31, ty = threadIdx.x >> 5;
    int n0 = blockIdx.x * 32, k0 = blockIdx.y * 32;
#pragma unroll
    for (int i = 0; i < 32; i += 8)
        t[ty + i][tx] = W[(size_t)(k0 + ty + i) * HH + n0 + tx];
    __syncthreads();
#pragma unroll
    for (int i = 0; i < 32; i += 8)
        out[(size_t)(n0 + ty + i) * HH + k0 + tx] = __float2half(t[tx][ty + i]);
}

// ---------------- fold gate weights: wA = w0+w2, wB = w1-w2 ----------------
__global__ __launch_bounds__(512) void prep_wb(const float* __restrict__ Wb)
{
    int l = blockIdx.x, j = threadIdx.x;
    const float* w = Wb + (size_t)l * 3 * HH;
    g_wbA[l * HH + j] = w[j] + w[2 * HH + j];
    g_wbB[l * HH + j] = w[HH + j] - w[2 * HH + j];
}

// ---------------- input projection (fp16 output only) ----------------
__global__ __launch_bounds__(256) void input_gemm(
    const float* __restrict__ A, const float* __restrict__ Wp,
    const float* __restrict__ bp)
{
    int n = blockIdx.x;
    __shared__ float a[FF];
    if (threadIdx.x < FF) a[threadIdx.x] = A[n * FF + threadIdx.x];
    __syncthreads();
    int j = threadIdx.x * 2;
    float2 acc = *(const float2*)(bp + j);
#pragma unroll
    for (int kk = 0; kk < FF; kk++) {
        float2 w = *(const float2*)(Wp + kk * HH + j);
        acc.x += a[kk] * w.x;
        acc.y += a[kk] * w.y;
    }
    *(__half2*)(g_xh + n * HH + j) = __floats2half2_rn(acc.x, acc.y);
}

// ---------------- fp16 mma.sync GEMM: 512 threads, 16 warps (4x4), warp 32x64
// CTA tile 128(M) x 256(N) x 64(K), 4-stage cp.async. regs=128, no spills.
#define ASH 72                                  // smem stride in halves
#define A_HALVES (128 * ASH)
#define B_HALVES (256 * ASH)
#define STAGE_HALVES (A_HALVES + B_HALVES)
#define GEMM_SMEM (4 * STAGE_HALVES * 2)

__global__ __launch_bounds__(512) void qkvs_gemm_mma(
    int layer,
    const float* __restrict__ bq, const float* __restrict__ bk,
    const float* __restrict__ bv, const float* __restrict__ bs_)
{
    extern __shared__ __half smh[];
    uint32_t smb = smem_u32(smh);

    int tid = threadIdx.x;
    int ntile = blockIdx.x;          // 0..1
    int mtile = blockIdx.y;          // 0..127
    int mat   = blockIdx.z;          // 0..3

    const float* bias = (mat == 0) ? bq : (mat == 1) ? bk : (mat == 2) ? bv : bs_;
    bias += (size_t)layer * HH + ntile * 256;
    __half* C = (mat == 0) ? g_q : (mat == 1) ? g_k : (mat == 2) ? g_v : g_s;
    const __half* Asrc = g_xh + (size_t)mtile * 128 * HH;
    const __half* Bsrc = g_wh + ((size_t)(layer * 4 + mat) * HH + ntile * 256) * HH;

    int w = tid >> 5, lane = tid & 31;
    int wm = w >> 2, wn = w & 3;                 // 4 x 4 warp grid
    int g = lane >> 2, tig = lane & 3;

    float acc[2][8][4];                          // warp tile 32 x 64
#pragma unroll
    for (int i = 0; i < 2; i++)
#pragma unroll
        for (int j = 0; j < 8; j++)
#pragma unroll
            for (int c = 0; c < 4; c++) acc[i][j][c] = 0.f;

    uint32_t a_lane_off = (uint32_t)(((wm * 32 + (lane & 15)) * ASH + (lane >> 4) * 8) * 2);
    uint32_t b_lane_off = (uint32_t)(A_HALVES * 2 +
        ((wn * 64 + (lane & 7) + (lane >> 4) * 8) * ASH + ((lane >> 3) & 1) * 8) * 2);

    auto load_stage = [&](int s, int buf) {
        int k0 = s * 64;
        uint32_t base = smb + (uint32_t)(buf * STAGE_HALVES) * 2;
#pragma unroll
        for (int i = 0; i < 2; i++) {            // A: 1024 chunks / 512 threads
            int q = tid + i * 512;
            int row = q >> 3, c = q & 7;
            cp_async16(base + (uint32_t)(row * ASH + c * 8) * 2,
                       Asrc + (size_t)row * HH + k0 + c * 8);
        }
#pragma unroll
        for (int i = 0; i < 4; i++) {            // B: 2048 chunks / 512 threads
            int q = tid + i * 512;
            int row = q >> 3, c = q & 7;
            cp_async16(base + (uint32_t)(A_HALVES + row * ASH + c * 8) * 2,
                       Bsrc + (size_t)row * HH + k0 + c * 8);
        }
        cp_commit();
    };

    auto compute = [&](int buf) {
        uint32_t stage = smb + (uint32_t)(buf * STAGE_HALVES) * 2;
        uint32_t abase = stage + a_lane_off;
        uint32_t bbase = stage + b_lane_off;
#pragma unroll
        for (int kk = 0; kk < 4; kk++) {         // 4 x k16
            uint32_t kbb = kk * 32;
            uint32_t af[2][4], bf[8][2];
#pragma unroll
            for (int i = 0; i < 2; i++)
                ldsm_x4(af[i], abase + (uint32_t)(i * 16 * ASH * 2) + kbb);
#pragma unroll
            for (int p = 0; p < 4; p++)
                ldsm_x4(&bf[p * 2][0], bbase + (uint32_t)(p * 16 * ASH * 2) + kbb);
#pragma unroll
            for (int i = 0; i < 2; i++)
#pragma unroll
                for (int j = 0; j < 8; j++) mma_f16(acc[i][j], af[i], bf[j]);
        }
    };

    load_stage(0, 0);
    load_stage(1, 1);
    load_stage(2, 2);

#pragma unroll
    for (int s = 0; s < 8; s++) {
        if (s < 6)      cp_wait<2>();
        else if (s == 6) cp_wait<1>();
        else             cp_wait<0>();
        __syncthreads();                         // also orders buf reuse (4-deep ring)
        if (s < 5) load_stage(s + 3, (s + 3) & 3);
        compute(s & 3);
    }

    // epilogue: add bias, store fp16
#pragma unroll
    for (int i = 0; i < 2; i++) {
        int row0 = mtile * 128 + wm * 32 + i * 16 + g;
#pragma unroll
        for (int j = 0; j < 8; j++) {
            int col = wn * 64 + j * 8 + 2 * tig;
            float bx = __ldg(&bias[col]), by = __ldg(&bias[col + 1]);
            __half2 o0 = __floats2half2_rn(acc[i][j][0] + bx, acc[i][j][1] + by);
            __half2 o1 = __floats2half2_rn(acc[i][j][2] + bx, acc[i][j][3] + by);
            *(__half2*)(C + (size_t)row0 * HH + ntile * 256 + col) = o0;
            *(__half2*)(C + (size_t)(row0 + 8) * HH + ntile * 256 + col) = o1;
        }
    }
}

// ---------------- fused attention + gate + residual + LayerNorm ----------------
// WARP-PER-NODE; all bulk loads hoisted (MLP ~16). Residual carried in fp16.
__global__ __launch_bounds__(128) void attn_gate_ln(
    const float* __restrict__ wbA, const float* __restrict__ wbB,
    const float* __restrict__ lg, const float* __restrict__ lb,
    float* __restrict__ dout, int is_last)
{
    int node = blockIdx.x * 4 + (threadIdx.x >> 5);
    int lane = threadIdx.x & 31;
    int e0 = lane * 16;                       // channel base

    int i = node >> 7, j = node & 127;
    int nb[4];
    float msk[4];
    nb[0] = (i > 0)   ? node - 128 : node;  msk[0] = (i > 0)   ? 0.f : -1e30f;
    nb[1] = (i < 127) ? node + 128 : node;  msk[1] = (i < 127) ? 0.f : -1e30f;
    nb[2] = (j > 0)   ? node - 1   : node;  msk[2] = (j > 0)   ? 0.f : -1e30f;
    nb[3] = (j < 127) ? node + 1   : node;  msk[3] = (j < 127) ? 0.f : -1e30f;

    // ======== hoisted loads: everything in flight at once ========
    const uint4* qp = (const uint4*)(g_q + (size_t)node * HH + e0);
    uint4 qa = qp[0], qb = qp[1];
    uint4 ka[4], kb2[4], va[4], vb[4];
#pragma unroll
    for (int t = 0; t < 4; t++) {
        const uint4* kp = (const uint4*)(g_k + (size_t)nb[t] * HH + e0);
        ka[t] = kp[0]; kb2[t] = kp[1];
    }
#pragma unroll
    for (int t = 0; t < 4; t++) {
        const uint4* vp = (const uint4*)(g_v + (size_t)nb[t] * HH + e0);
        va[t] = vp[0]; vb[t] = vp[1];
    }
    const uint4* sp = (const uint4*)(g_s + (size_t)node * HH + e0);
    uint4 sa = sp[0], sb = sp[1];
    const uint4* xp = (const uint4*)(g_xh + (size_t)node * HH + e0);
    uint4 xa = xp[0], xb = xp[1];
    float4 wA0 = ((const float4*)(wbA + e0))[0];
    float4 wA1 = ((const float4*)(wbA + e0))[1];
    float4 wA2 = ((const float4*)(wbA + e0))[2];
    float4 wA3 = ((const float4*)(wbA + e0))[3];
    float4 wB0 = ((const float4*)(wbB + e0))[0];
    float4 wB1 = ((const float4*)(wbB + e0))[1];
    float4 wB2 = ((const float4*)(wbB + e0))[2];
    float4 wB3 = ((const float4*)(wbB + e0))[3];

    // ======== dots + softmax ========
    float qf[16];
    h8f(qa, qf); h8f(qb, qf + 8);
    float d[4];
#pragma unroll
    for (int t = 0; t < 4; t++) {
        float kf[16];
        h8f(ka[t], kf); h8f(kb2[t], kf + 8);
        float s = 0.f;
#pragma unroll
        for (int e = 0; e < 16; e++) s += qf[e] * kf[e];
        d[t] = s;
    }
#pragma unroll
    for (int t = 0; t < 4; t++) {
        d[t] += __shfl_xor_sync(0xffffffffu, d[t], 1);
        d[t] += __shfl_xor_sync(0xffffffffu, d[t], 2);
        d[t] = d[t] * 0.125f + msk[t];
    }
    float m = fmaxf(fmaxf(d[0], d[1]), fmaxf(d[2], d[3]));
    float w0 = expf(d[0] - m), w1 = expf(d[1] - m);
    float w2 = expf(d[2] - m), w3 = expf(d[3] - m);
    float inv = 1.f / (w0 + w1 + w2 + w3 + 1e-16f);
    float wt[4] = {w0 * inv, w1 * inv, w2 * inv, w3 * inv};

    // ======== weighted V ========
    float o[16];
#pragma unroll
    for (int e = 0; e < 16; e++) o[e] = 0.f;
#pragma unroll
    for (int t = 0; t < 4; t++) {
        float vf[16];
        h8f(va[t], vf); h8f(vb[t], vf + 8);
#pragma unroll
        for (int e = 0; e < 16; e++) o[e] += wt[t] * vf[e];
    }

    // ======== gate (folded weights) ========
    float rv[16];
    h8f(sa, rv); h8f(sb, rv + 8);
    float wA[16] = {wA0.x, wA0.y, wA0.z, wA0.w, wA1.x, wA1.y, wA1.z, wA1.w,
                    wA2.x, wA2.y, wA2.z, wA2.w, wA3.x, wA3.y, wA3.z, wA3.w};
    float wB[16] = {wB0.x, wB0.y, wB0.z, wB0.w, wB1.x, wB1.y, wB1.z, wB1.w,
                    wB2.x, wB2.y, wB2.z, wB2.w, wB3.x, wB3.y, wB3.z, wB3.w};
    float part = 0.f;
#pragma unroll
    for (int e = 0; e < 16; e++) part += o[e] * wA[e] + rv[e] * wB[e];
#pragma unroll
    for (int s = 16; s; s >>= 1) part += __shfl_xor_sync(0xffffffffu, part, s);
    float gate = 1.f / (1.f + expf(-part));

    // ======== residual + LN ========
    float xf[16];
    h8f(xa, xf); h8f(xb, xf + 8);
    float tx[16];
    float s1 = 0.f, s2 = 0.f;
#pragma unroll
    for (int e = 0; e < 16; e++) {
        float t = xf[e] + gate * rv[e] + (1.f - gate) * o[e];
        tx[e] = t;
        s1 += t;
        s2 += t * t;
    }
#pragma unroll
    for (int s = 16; s; s >>= 1) {
        s1 += __shfl_xor_sync(0xffffffffu, s1, s);
        s2 += __shfl_xor_sync(0xffffffffu, s2, s);
    }
    float mu   = s1 * (1.f / HH);
    float var  = s2 * (1.f / HH) - mu * mu;
    float rstd = rsqrtf(var + 1e-5f);

#pragma unroll
    for (int c = 0; c < 4; c++) {
        float4 gg = ((const float4*)(lg + e0))[c];
        float4 bb = ((const float4*)(lb + e0))[c];
        float4 ov;
        ov.x = (tx[c*4+0] - mu) * rstd * gg.x + bb.x;
        ov.y = (tx[c*4+1] - mu) * rstd * gg.y + bb.y;
        ov.z = (tx[c*4+2] - mu) * rstd * gg.z + bb.z;
        ov.w = (tx[c*4+3] - mu) * rstd * gg.w + bb.w;
        if (is_last) {
            ((float4*)(dout + (size_t)node * HH + e0))[c] = ov;
        } else {
            __half2 h0 = __floats2half2_rn(ov.x, ov.y);
            __half2 h1 = __floats2half2_rn(ov.z, ov.w);
            ((__half2*)(g_xh + (size_t)node * HH + e0))[c * 2]     = h0;
            ((__half2*)(g_xh + (size_t)node * HH + e0))[c * 2 + 1] = h1;
        }
    }
}

// ---------------- global mean ----------------
__global__ __launch_bounds__(256) void mean_stage1(const float* __restrict__ x)
{
    int b = blockIdx.x;                      // 0..511, rows b*32..b*32+31
    int j = threadIdx.x * 2;
    float2 acc = {0.f, 0.f};
    const float* xp = x + (size_t)b * 32 * HH;
    for (int r = 0; r < 32; r++) {
        float2 v2 = *(const float2*)(xp + (size_t)r * HH + j);
        acc.x += v2.x;
        acc.y += v2.y;
    }
    *(float2*)(g_part + (size_t)b * HH + j) = acc;
}

__global__ __launch_bounds__(256) void mean_stage2(float* __restrict__ emb)
{
    int j = blockIdx.x * 256 + threadIdx.x;
    float acc = 0.f;
    for (int b = 0; b < 512; b++) acc += g_part[(size_t)b * HH + j];
    emb[j] = acc * (1.f / NN);
}

// ---------------- launch ----------------
extern "C" void kernel_launch(void* const* d_in, const int* in_sizes, int n_in,
                              void* d_out, int out_size)
{
    const float* graph = (const float*)d_in[0];
    const float* Wp = (const float*)d_in[3];
    const float* bp = (const float*)d_in[4];
    const float* Wq = (const float*)d_in[5];
    const float* bq = (const float*)d_in[6];
    const float* Wk = (const float*)d_in[7];
    const float* bk = (const float*)d_in[8];
    const float* Wv = (const float*)d_in[9];
    const float* bv = (const float*)d_in[10];
    const float* Ws = (const float*)d_in[11];
    const float* bs = (const float*)d_in[12];
    const float* Wb = (const float*)d_in[13];
    const float* lg = (const float*)d_in[14];
    const float* lb = (const float*)d_in[15];
    float* out = (float*)d_out;

    static int smem_set = 0;
    if (!smem_set) {
        cudaFuncSetAttribute(qkvs_gemm_mma, cudaFuncAttributeMaxDynamicSharedMemorySize,
                             GEMM_SMEM);
        smem_set = 1;
    }

    transpose_w<<<dim3(16, 16, 16), 256>>>(Wq, Wk, Wv, Ws);
    prep_wb<<<4, 512>>>(Wb);
    input_gemm<<<NN, 256>>>(graph, Wp, bp);

    float* wbA_dev = nullptr;
    float* wbB_dev = nullptr;
    cudaGetSymbolAddress((void**)&wbA_dev, g_wbA);
    cudaGetSymbolAddress((void**)&wbB_dev, g_wbB);

    for (int l = 0; l < 4; l++) {
        size_t bOff = (size_t)l * HH;
        qkvs_gemm_mma<<<dim3(2, 128, 4), 512, GEMM_SMEM>>>(l, bq, bk, bv, bs);
        attn_gate_ln<<<NN / 4, 128>>>(wbA_dev + bOff, wbB_dev + bOff,
                                      lg + bOff, lb + bOff,
                                      out, (l == 3) ? 1 : 0);
    }

    mean_stage1<<<512, 256>>>(out);
    mean_stage2<<<2, 256>>>(out + (size_t)NN * HH);
}